// round 2
// baseline (speedup 1.0000x reference)
#include <cuda_runtime.h>
#include <cuda_bf16.h>

#define T_LEN 1024
#define C_DIM 8
#define B_SZ  64
#define ALPHA_ 0.7f
#define GAMMA_ 0.2f
#define INVG_  5.0f           // 1/GAMMA
#define INF_   1000000000.0f

#define MSE_BLOCKS 256

__device__ float g_mse_partial[MSE_BLOCKS];
__device__ float g_sdtw[B_SZ];

// ---------------------------------------------------------------------------
// MSE partial sums: grid-stride, vectorized, deterministic per-block partials.
// ---------------------------------------------------------------------------
__global__ void mse_kernel(const float* __restrict__ p,
                           const float* __restrict__ t, int n4) {
    const float4* p4 = (const float4*)p;
    const float4* t4 = (const float4*)t;
    float acc = 0.f;
    for (int idx = blockIdx.x * blockDim.x + threadIdx.x; idx < n4;
         idx += gridDim.x * blockDim.x) {
        float4 a = p4[idx], b = t4[idx];
        float dx = a.x - b.x, dy = a.y - b.y, dz = a.z - b.z, dw = a.w - b.w;
        acc = fmaf(dx, dx, acc);
        acc = fmaf(dy, dy, acc);
        acc = fmaf(dz, dz, acc);
        acc = fmaf(dw, dw, acc);
    }
#pragma unroll
    for (int o = 16; o; o >>= 1) acc += __shfl_xor_sync(0xffffffffu, acc, o);
    __shared__ float ws[8];
    if ((threadIdx.x & 31) == 0) ws[threadIdx.x >> 5] = acc;
    __syncthreads();
    if (threadIdx.x == 0) {
        float v = 0.f;
#pragma unroll
        for (int w = 0; w < 8; ++w) v += ws[w];
        g_mse_partial[blockIdx.x] = v;
    }
}

// ---------------------------------------------------------------------------
// Soft-DTW: one CTA per batch, anti-diagonal wavefront, thread i owns row i.
// SMEM: target tile (row stride 36 floats -> conflict-free diagonal reads),
//       y2[], and 3 rotating R buffers with INF sentinel at slot 0.
// ---------------------------------------------------------------------------
__global__ __launch_bounds__(1024, 1)
void sdtw_kernel(const float* __restrict__ pred,
                 const float* __restrict__ target) {
    extern __shared__ float sm[];
    float* tg = sm;                      // T_LEN * 36
    float* y2 = tg + T_LEN * 36;         // T_LEN
    float* rb = y2 + T_LEN;              // 3 * (T_LEN + 1)

    const int i = threadIdx.x;
    const int b = blockIdx.x;

    const float4* pg = (const float4*)(pred + (size_t)b * T_LEN * C_DIM);
    const float4* gg = (const float4*)(target + (size_t)b * T_LEN * C_DIM);

    float4 p0 = pg[2 * i];
    float4 p1 = pg[2 * i + 1];
    float4 t0 = gg[2 * i];
    float4 t1 = gg[2 * i + 1];

    ((float4*)(tg + i * 36))[0] = t0;
    ((float4*)(tg + i * 36 + 4))[0] = t1;
    y2[i] = t0.x * t0.x + t0.y * t0.y + t0.z * t0.z + t0.w * t0.w +
            t1.x * t1.x + t1.y * t1.y + t1.z * t1.z + t1.w * t1.w;
    const float x2 = p0.x * p0.x + p0.y * p0.y + p0.z * p0.z + p0.w * p0.w +
                     p1.x * p1.x + p1.y * p1.y + p1.z * p1.z + p1.w * p1.w;

    // init all three R buffers (incl. sentinels at slot 0) to INF
    for (int idx = i; idx < 3 * (T_LEN + 1); idx += 1024) rb[idx] = INF_;
    __syncthreads();

    float* km2 = rb;                       // r_{k-2}, slot s holds index s-1
    float* km1 = rb + (T_LEN + 1);         // r_{k-1}
    float* W   = rb + 2 * (T_LEN + 1);     // r_k being written

    float last = INF_;

    for (int k = 0; k < 2 * T_LEN - 1; ++k) {
        const int j = k - i;
        float val = INF_;
        if ((unsigned)j < (unsigned)T_LEN) {
            const float4* tr = (const float4*)(tg + j * 36);
            float4 a = tr[0];
            float4 c = tr[1];
            float dot = fmaf(p0.x, a.x,
                        fmaf(p0.y, a.y,
                        fmaf(p0.z, a.z,
                        fmaf(p0.w, a.w,
                        fmaf(p1.x, c.x,
                        fmaf(p1.y, c.y,
                        fmaf(p1.z, c.z, p1.w * c.w)))))));
            float d = x2 + y2[j] - 2.f * dot;

            float up   = km1[i];       // r_{k-1}[i-1]
            float left = km1[i + 1];   // r_{k-1}[i]
            float diag = km2[i];       // r_{k-2}[i-1]
            if (k == 0 && i == 0) diag = 0.f;

            float mn = fminf(up, fminf(left, diag));
            float s  = __expf((mn - up)   * INVG_)
                     + __expf((mn - left) * INVG_)
                     + __expf((mn - diag) * INVG_);
            val = d + mn - GAMMA_ * __logf(s);
        }
        W[i + 1] = val;
        last = val;
        __syncthreads();
        float* tmp = km2; km2 = km1; km1 = W; W = tmp;
    }

    if (i == T_LEN - 1) g_sdtw[b] = last;   // R[T-1][T-1]
}

// ---------------------------------------------------------------------------
// Final deterministic reduction -> out[0]
// ---------------------------------------------------------------------------
__global__ void final_kernel(float* __restrict__ out) {
    const int t = threadIdx.x;  // 256
    float m  = g_mse_partial[t];
    float sd = (t < B_SZ) ? g_sdtw[t] : 0.f;
#pragma unroll
    for (int o = 16; o; o >>= 1) {
        m  += __shfl_xor_sync(0xffffffffu, m, o);
        sd += __shfl_xor_sync(0xffffffffu, sd, o);
    }
    __shared__ float sm_[8], ss_[8];
    if ((t & 31) == 0) { sm_[t >> 5] = m; ss_[t >> 5] = sd; }
    __syncthreads();
    if (t == 0) {
        float M = 0.f, S = 0.f;
#pragma unroll
        for (int w = 0; w < 8; ++w) { M += sm_[w]; S += ss_[w]; }
        float mse  = M / (float)(B_SZ * T_LEN * C_DIM);
        float sdtw = S / (float)B_SZ;
        out[0] = ALPHA_ * mse + (1.0f - ALPHA_) * sdtw;
    }
}

// ---------------------------------------------------------------------------
extern "C" void kernel_launch(void* const* d_in, const int* in_sizes, int n_in,
                              void* d_out, int out_size) {
    const float* pred   = (const float*)d_in[0];
    const float* target = (const float*)d_in[1];
    float* out = (float*)d_out;

    const int n4 = (B_SZ * T_LEN * C_DIM) / 4;
    mse_kernel<<<MSE_BLOCKS, 256>>>(pred, target, n4);

    const int smem = (T_LEN * 36 + T_LEN + 3 * (T_LEN + 1)) * (int)sizeof(float);
    cudaFuncSetAttribute(sdtw_kernel,
                         cudaFuncAttributeMaxDynamicSharedMemorySize, smem);
    sdtw_kernel<<<B_SZ, 1024, smem>>>(pred, target);

    final_kernel<<<1, 256>>>(out);
}